// round 7
// baseline (speedup 1.0000x reference)
#include <cuda_runtime.h>
#include <cstdint>

typedef unsigned long long u64;

// ---------------- config ----------------
constexpr int TPB = 576;     // 18 warps
constexpr int EPB = 128;     // edges per block

// smem layout (float offsets)
constexpr int SM_W0  = 0;                     // 40 x 68 (prescaled S0)
constexpr int SM_BP  = 2720;                  // 64 x 288 packed B
constexpr int SM_HD  = SM_BP + 64 * 288;      // 21152 : h_dup 64 x 128 float2
constexpr int SM_TP  = SM_HD + 2 * 64 * 128;  // 37536 : 128 x 17 tp scalars
constexpr int SM_CST = SM_TP + 128 * 17;      // 39712 : bessel_w[8], tpw[7]
constexpr int SMEM_FLOATS = SM_CST + 16;
constexpr int SMEM_BYTES  = SMEM_FLOATS * 4;  // 158,912 B

// ---------------- device scratch ----------------
__device__ float g_wcombo[64 * 160];
__device__ float g_bpack[64 * 288];

// ---------------- f32x2 helpers ----------------
__device__ __forceinline__ u64 pk2(float lo, float hi) {
    u64 r; asm("mov.b64 %0, {%1, %2};" : "=l"(r) : "f"(lo), "f"(hi)); return r;
}
__device__ __forceinline__ void up2(float& lo, float& hi, u64 a) {
    asm("mov.b64 {%0, %1}, %2;" : "=f"(lo), "=f"(hi) : "l"(a));
}
__device__ __forceinline__ u64 fma2(u64 a, u64 b, u64 c) {
    u64 d; asm("fma.rn.f32x2 %0, %1, %2, %3;" : "=l"(d) : "l"(a), "l"(b), "l"(c)); return d;
}
__device__ __forceinline__ float silu_f(float v) { return v / (1.0f + __expf(-v)); }

// ---------------- prep 1: W_combo = (W1*S1) @ (We*S2) ----------------
__global__ void combo_kernel(const float* __restrict__ W1, const float* __restrict__ We) {
    constexpr float S1 = 1.6789f * 0.125f;
    constexpr float S2 = 0.08838834764831845f;
    int idx = blockIdx.x * blockDim.x + threadIdx.x;
    if (idx >= 64 * 160) return;
    int r = idx / 160, c = idx % 160;
    float acc = 0.0f;
#pragma unroll 8
    for (int k = 0; k < 128; k++) acc = fmaf(W1[r * 128 + k], We[k * 160 + c], acc);
    g_wcombo[idx] = acc * (S1 * S2);
}

// ---------------- prep 2: pack B = [W1*S1 | WC reordered] ----------------
// cols 0..127   : latents (W1[j][c] * S1)
// cols 128..191 : interleaved (w0a[m], w0b[m]) = (WC[j][m], WC[j][32+m])
// cols 192..255 : interleaved (w1a[m], w1b[m]) = (WC[j][64+m], WC[j][96+m])
// cols 256..287 : w2[m] = WC[j][128+m]
__global__ void pack_kernel(const float* __restrict__ W1) {
    constexpr float S1 = 1.6789f * 0.125f;
    int idx = blockIdx.x * blockDim.x + threadIdx.x;
    if (idx >= 64 * 288) return;
    int j = idx / 288, c = idx % 288;
    float v;
    if (c < 128)        v = W1[j * 128 + c] * S1;
    else if (c < 192) { int m = (c - 128) >> 1, s = (c - 128) & 1; v = g_wcombo[j * 160 + m + 32 * s]; }
    else if (c < 256) { int m = (c - 192) >> 1, s = (c - 192) & 1; v = g_wcombo[j * 160 + 64 + m + 32 * s]; }
    else                v = g_wcombo[j * 160 + 128 + (c - 256)];
    g_bpack[idx] = v;
}

// ---------------- main kernel ----------------
__global__ void __launch_bounds__(TPB, 1)
e3_gemm_kernel(const int*   __restrict__ eidx,
               const float* __restrict__ esh,
               const float* __restrict__ elen,
               const float* __restrict__ onehot,
               const float* __restrict__ bw,
               const float* __restrict__ tpw,
               const float* __restrict__ W0,
               float*       __restrict__ out,
               int E)
{
    extern __shared__ float sm[];
    constexpr float S0   = 0.15811388300841897f;     // 1/sqrt(40)
    constexpr float SQ3  = 1.7320508075688772f;
    constexpr float INV2 = 0.70710678118654752f;

    const int tid = threadIdx.x;

    // ---- cooperative loads ----
    for (int i = tid; i < 40 * 64; i += TPB) {
        int r = i >> 6, k = i & 63;
        sm[SM_W0 + r * 68 + k] = W0[i] * S0;
    }
    for (int i = tid; i < 64 * 288; i += TPB) sm[SM_BP + i] = g_bpack[i];
    if (tid < 8)       sm[SM_CST + tid] = bw[tid];
    else if (tid < 15) sm[SM_CST + tid] = tpw[tid - 8];
    __syncthreads();

    const size_t ebg = (size_t)blockIdx.x * EPB;
    float* __restrict__ lat_out  = out;
    float* __restrict__ feat_out = out + (size_t)E * 128;
    float* __restrict__ cut_out  = out + (size_t)E * 416;

    // ================= stage 1: first 128 threads, one edge each =================
    if (tid < EPB) {
        const int el = tid;
        const int e  = (int)ebg + el;
        const int   src = eidx[e];
        const int   dst = eidx[E + e];
        const float r   = elen[e];
        const float4 shv = reinterpret_cast<const float4*>(esh)[e];

        int ts = 0, td = 0;
        {
            const float4* rs = reinterpret_cast<const float4*>(onehot + (size_t)src * 16);
            const float4* rd = reinterpret_cast<const float4*>(onehot + (size_t)dst * 16);
#pragma unroll
            for (int q4 = 0; q4 < 4; q4++) {
                float4 a = __ldg(rs + q4); float4 b = __ldg(rd + q4);
                int base = q4 * 4;
                if (a.x > 0.5f) ts = base;     if (a.y > 0.5f) ts = base + 1;
                if (a.z > 0.5f) ts = base + 2; if (a.w > 0.5f) ts = base + 3;
                if (b.x > 0.5f) td = base;     if (b.y > 0.5f) td = base + 1;
                if (b.z > 0.5f) td = base + 2; if (b.w > 0.5f) td = base + 3;
            }
        }

        const float x    = r * 0.2f;
        const float invr = 1.0f / r;
        float eb[8];
#pragma unroll
        for (int j = 0; j < 8; j++)
            eb[j] = 0.4f * __sinf(sm[SM_CST + j] * x) * invr;

        const float x3 = x * x * x, x6 = x3 * x3, x7 = x6 * x, x8 = x7 * x;
        const float poly = 1.0f - 28.0f * x6 + 48.0f * x7 - 21.0f * x8;
        const float cutv = (x < 1.0f) ? poly : 0.0f;
        const float cl   = (cutv > 0.0f) ? cutv : 0.0f;
        cut_out[e] = cutv;

        // h = silu( W0s[ts] + W0s[16+td] + eb @ W0s[32..39] )
        float h[64];
        const float* w0s = sm + SM_W0 + ts * 68;
        const float* w0d = sm + SM_W0 + (16 + td) * 68;
#pragma unroll
        for (int k = 0; k < 64; k++) h[k] = w0s[k] + w0d[k];
#pragma unroll
        for (int j = 0; j < 8; j++) {
            const float bj = eb[j];
            const float* wr = sm + SM_W0 + (32 + j) * 68;
#pragma unroll
            for (int k = 0; k < 64; k++) h[k] = fmaf(bj, wr[k], h[k]);
        }

        // write h_dup[j][el] = (h, h)
        float2* hd = reinterpret_cast<float2*>(sm + SM_HD);
#pragma unroll
        for (int j = 0; j < 64; j++) {
            float hv = silu_f(h[j]);
            hd[j * 128 + el] = make_float2(hv, hv);
        }

        // tp scalars (cl + INV2 folded)
        const float s = shv.x, vx = shv.y, vy = shv.z, vz = shv.w;
        const float tw0 = sm[SM_CST +  8], tw1 = sm[SM_CST +  9], tw2 = sm[SM_CST + 10];
        const float tw3 = sm[SM_CST + 11], tw4 = sm[SM_CST + 12], tw5 = sm[SM_CST + 13];
        const float tw6 = sm[SM_CST + 14];
        const float sq   = s * s;
        const float dotv = (vx * vx + vy * vy + vz * vz) * (1.0f / SQ3);
        float* tp = sm + SM_TP + el * 17;
        tp[0] = cl;
        tp[1] = INV2 * (tw0 * sq + tw1 * dotv) * cl;
        tp[2] = INV2 * (tw4 * sq + tw5 * dotv) * cl;
        const float sa = INV2 * tw2 * s * cl;
        const float sb = INV2 * tw3 * s * cl;
        tp[3] = sa * vx; tp[4] = sa * vy; tp[5] = sa * vz;
        tp[6] = sb * vx; tp[7] = sb * vy; tp[8] = sb * vz;
        const float t6c = tw6 * cl;
        tp[9]  = t6c * SQ3 * vx * vy;
        tp[10] = t6c * SQ3 * vy * vz;
        tp[11] = t6c * (vz * vz - 0.5f * (vx * vx + vy * vy));
        tp[12] = t6c * SQ3 * vx * vz;
        tp[13] = t6c * (0.5f * SQ3) * (vx * vx - vy * vy);
    }
    __syncthreads();

    // ================= GEMM: warp w -> cols 16w..16w+15, lane -> edges 4l..4l+3 =================
    const int warp = tid >> 5;
    const int lane = tid & 31;
    const int c0   = warp * 16;

    u64 acc[4][8];
#pragma unroll
    for (int ei = 0; ei < 4; ei++)
#pragma unroll
        for (int q = 0; q < 8; q++) acc[ei][q] = 0ull;

    const char* wbase = reinterpret_cast<const char*>(sm + SM_BP + c0);
    const char* hbase = reinterpret_cast<const char*>(sm + SM_HD) + lane * 32;

#pragma unroll 4
    for (int j = 0; j < 64; j++) {
        const ulonglong2 hA = *reinterpret_cast<const ulonglong2*>(hbase + j * 1024);
        const ulonglong2 hB = *reinterpret_cast<const ulonglong2*>(hbase + j * 1024 + 16);
        const ulonglong2* wr = reinterpret_cast<const ulonglong2*>(wbase + j * 1152);
#pragma unroll
        for (int q2 = 0; q2 < 4; q2++) {
            const ulonglong2 w = wr[q2];
            acc[0][2 * q2]     = fma2(hA.x, w.x, acc[0][2 * q2]);
            acc[0][2 * q2 + 1] = fma2(hA.x, w.y, acc[0][2 * q2 + 1]);
            acc[1][2 * q2]     = fma2(hA.y, w.x, acc[1][2 * q2]);
            acc[1][2 * q2 + 1] = fma2(hA.y, w.y, acc[1][2 * q2 + 1]);
            acc[2][2 * q2]     = fma2(hB.x, w.x, acc[2][2 * q2]);
            acc[2][2 * q2 + 1] = fma2(hB.x, w.y, acc[2][2 * q2 + 1]);
            acc[3][2 * q2]     = fma2(hB.y, w.x, acc[3][2 * q2]);
            acc[3][2 * q2 + 1] = fma2(hB.y, w.y, acc[3][2 * q2 + 1]);
        }
    }

    // ================= epilogue by warp class =================
    if (warp < 8) {
        // latents: out col c0..c0+15, scaled by cl
#pragma unroll
        for (int ei = 0; ei < 4; ei++) {
            const int el = 4 * lane + ei;
            const float cl = sm[SM_TP + el * 17];
            float* dst = lat_out + (ebg + el) * 128 + c0;
#pragma unroll
            for (int t = 0; t < 4; t++) {
                float a0, a1, a2, a3;
                up2(a0, a1, acc[ei][2 * t]);
                up2(a2, a3, acc[ei][2 * t + 1]);
                reinterpret_cast<float4*>(dst)[t] =
                    make_float4(a0 * cl, a1 * cl, a2 * cl, a3 * cl);
            }
        }
    } else if (warp < 12) {
        // f0: pairs -> feat cols 8*(warp-8) + q, q=0..7
        const int m0 = 8 * (warp - 8);
#pragma unroll
        for (int ei = 0; ei < 4; ei++) {
            const int el = 4 * lane + ei;
            const float* tp = sm + SM_TP + el * 17;
            const float t0a = tp[1], t0b = tp[2];
            float v[8];
#pragma unroll
            for (int q = 0; q < 8; q++) {
                float a, b; up2(a, b, acc[ei][q]);
                v[q] = a * t0a + b * t0b;
            }
            float* dst = feat_out + (ebg + el) * 288 + m0;
            reinterpret_cast<float4*>(dst)[0] = make_float4(v[0], v[1], v[2], v[3]);
            reinterpret_cast<float4*>(dst)[1] = make_float4(v[4], v[5], v[6], v[7]);
        }
    } else if (warp < 16) {
        // f1: pairs -> 3 outputs each; feat cols 32 + 24*(warp-12) + (3q+i)
        const int b0 = 32 + 24 * (warp - 12);
#pragma unroll
        for (int ei = 0; ei < 4; ei++) {
            const int el = 4 * lane + ei;
            const float* tp = sm + SM_TP + el * 17;
            const float a0 = tp[3], a1 = tp[4], a2 = tp[5];
            const float b0v = tp[6], b1v = tp[7], b2v = tp[8];
            float v[24];
#pragma unroll
            for (int q = 0; q < 8; q++) {
                float a, b; up2(a, b, acc[ei][q]);
                v[3 * q + 0] = a * a0 + b * b0v;
                v[3 * q + 1] = a * a1 + b * b1v;
                v[3 * q + 2] = a * a2 + b * b2v;
            }
            float* dst = feat_out + (ebg + el) * 288 + b0;
#pragma unroll
            for (int t = 0; t < 6; t++)
                reinterpret_cast<float4*>(dst)[t] =
                    make_float4(v[4 * t], v[4 * t + 1], v[4 * t + 2], v[4 * t + 3]);
        }
    } else {
        // f2: 16 w2 values -> 5 outputs each; feat cols 128 + 80*(warp-16) + (5k+i)
        const int b0 = 128 + 80 * (warp - 16);
#pragma unroll
        for (int ei = 0; ei < 4; ei++) {
            const int el = 4 * lane + ei;
            const float* tp = sm + SM_TP + el * 17;
            float tp2[5];
#pragma unroll
            for (int i = 0; i < 5; i++) tp2[i] = tp[9 + i];
            float* dst = feat_out + (ebg + el) * 288 + b0;
#pragma unroll
            for (int half = 0; half < 2; half++) {
                float v[40];
#pragma unroll
                for (int q = 0; q < 4; q++) {
                    float a, b; up2(a, b, acc[ei][4 * half + q]);
#pragma unroll
                    for (int i = 0; i < 5; i++) {
                        v[10 * q + i]     = a * tp2[i];
                        v[10 * q + 5 + i] = b * tp2[i];
                    }
                }
#pragma unroll
                for (int t = 0; t < 10; t++)
                    reinterpret_cast<float4*>(dst + 40 * half)[t] =
                        make_float4(v[4 * t], v[4 * t + 1], v[4 * t + 2], v[4 * t + 3]);
            }
        }
    }
}

extern "C" void kernel_launch(void* const* d_in, const int* in_sizes, int n_in,
                              void* d_out, int out_size)
{
    const int*   eidx   = (const int*)  d_in[0];
    const float* esh    = (const float*)d_in[1];
    const float* elen   = (const float*)d_in[2];
    const float* onehot = (const float*)d_in[3];
    const float* bw     = (const float*)d_in[4];
    const float* tpw    = (const float*)d_in[5];
    const float* W0     = (const float*)d_in[6];
    const float* W1     = (const float*)d_in[7];
    const float* We     = (const float*)d_in[8];
    float* out = (float*)d_out;

    const int E = in_sizes[0] / 2;       // 524288
    const int blocks = E / EPB;          // 4096

    combo_kernel<<<(64 * 160 + 255) / 256, 256>>>(W1, We);
    pack_kernel<<<(64 * 288 + 255) / 256, 256>>>(W1);

    cudaFuncSetAttribute(e3_gemm_kernel,
                         cudaFuncAttributeMaxDynamicSharedMemorySize, SMEM_BYTES);
    e3_gemm_kernel<<<blocks, TPB, SMEM_BYTES>>>(
        eidx, esh, elen, onehot, bw, tpw, W0, out, E);
}

// round 8
// speedup vs baseline: 1.5499x; 1.5499x over previous
#include <cuda_runtime.h>
#include <cstdint>

typedef unsigned long long u64;

// ---------------- constants ----------------
constexpr int THREADS = 512;
constexpr int WARPS   = THREADS / 32;
constexpr int BSTRIDE = 36;                 // buf row stride (floats): 16B-aligned, conflict-free

// smem layout (floats)
constexpr int SM_W0   = 0;                  // 40 rows x stride 68
constexpr int SM_W1   = 40 * 68;            // 2720 : 64 x 128 (prescaled S1)
constexpr int SM_WC   = SM_W1 + 64 * 128;   // 10912 : 64 x 160 (W1s @ We s)
constexpr int SM_CST  = SM_WC + 64 * 160;   // 21152 : bessel_w[8], tpw[7]
constexpr int SM_BUF  = SM_CST + 16;        // 21168 : WARPS * 32 * 36
constexpr int SMEM_FLOATS = SM_BUF + WARPS * 32 * BSTRIDE;
constexpr int SMEM_BYTES  = SMEM_FLOATS * 4;   // 158,400 B

// ---------------- device scratch ----------------
__device__ float g_wcombo[64 * 160];

// ---------------- f32x2 helpers ----------------
__device__ __forceinline__ u64 pk2(float lo, float hi) {
    u64 r; asm("mov.b64 %0, {%1, %2};" : "=l"(r) : "f"(lo), "f"(hi)); return r;
}
__device__ __forceinline__ void up2(float& lo, float& hi, u64 a) {
    asm("mov.b64 {%0, %1}, %2;" : "=f"(lo), "=f"(hi) : "l"(a));
}
__device__ __forceinline__ u64 fma2(u64 a, u64 b, u64 c) {
    u64 d; asm("fma.rn.f32x2 %0, %1, %2, %3;" : "=l"(d) : "l"(a), "l"(b), "l"(c)); return d;
}
__device__ __forceinline__ u64 add2(u64 a, u64 b) {
    u64 d; asm("add.rn.f32x2 %0, %1, %2;" : "=l"(d) : "l"(a), "l"(b)); return d;
}
__device__ __forceinline__ u64 mul2(u64 a, u64 b) {
    u64 d; asm("mul.rn.f32x2 %0, %1, %2;" : "=l"(d) : "l"(a), "l"(b)); return d;
}
__device__ __forceinline__ float silu_f(float v) { return v / (1.0f + __expf(-v)); }

// vectorized drain: 32 rows x 32 cols window -> coalesced STG.128
__device__ __forceinline__ void drain32(const float* __restrict__ buf,
                                        float* __restrict__ dstbase,
                                        int stride_f, int ebase, int col0, int lane) {
    const int rofs = lane >> 3;
    const int c    = (lane & 7) * 4;
#pragma unroll
    for (int g = 0; g < 8; g++) {
        const int rr = 4 * g + rofs;
        float4 v = *reinterpret_cast<const float4*>(buf + rr * BSTRIDE + c);
        *reinterpret_cast<float4*>(dstbase + (size_t)(ebase + rr) * stride_f + col0 + c) = v;
    }
}

// ---------------- precompute W_combo = (W1*S1) @ (We*S2) ----------------
__global__ void combo_kernel(const float* __restrict__ W1, const float* __restrict__ We) {
    constexpr float S1 = 1.6789f * 0.125f;
    constexpr float S2 = 0.08838834764831845f;
    int idx = blockIdx.x * blockDim.x + threadIdx.x;
    if (idx >= 64 * 160) return;
    int r = idx / 160, c = idx % 160;
    float acc = 0.0f;
#pragma unroll 8
    for (int k = 0; k < 128; k++) acc = fmaf(W1[r * 128 + k], We[k * 160 + c], acc);
    g_wcombo[idx] = acc * (S1 * S2);
}

__global__ void __launch_bounds__(THREADS, 1)
e3_fused_kernel(const int*   __restrict__ eidx,
                const float* __restrict__ esh,
                const float* __restrict__ elen,
                const float* __restrict__ onehot,
                const float* __restrict__ bw,
                const float* __restrict__ tpw,
                const float* __restrict__ W0,
                const float* __restrict__ W1,
                float*       __restrict__ out,
                int E)
{
    extern __shared__ float sm[];

    constexpr float S0 = 0.15811388300841897f;   // 1/sqrt(40)
    constexpr float S1 = 1.6789f * 0.125f;       // SILU_CST/sqrt(64)

    // ---- cooperative weight load (pre-scaled) ----
    for (int i = threadIdx.x; i < 40 * 64; i += THREADS) {
        int r = i >> 6, k = i & 63;
        sm[SM_W0 + r * 68 + k] = W0[i] * S0;
    }
    for (int i = threadIdx.x; i < 64 * 128; i += THREADS) sm[SM_W1 + i] = W1[i] * S1;
    for (int i = threadIdx.x; i < 64 * 160; i += THREADS) sm[SM_WC + i] = g_wcombo[i];
    if (threadIdx.x < 8)       sm[SM_CST + threadIdx.x] = bw[threadIdx.x];
    else if (threadIdx.x < 15) sm[SM_CST + threadIdx.x] = tpw[threadIdx.x - 8];
    __syncthreads();

    const int lane  = threadIdx.x & 31;
    const int warp  = threadIdx.x >> 5;
    float* buf = sm + SM_BUF + warp * (32 * BSTRIDE);
    float* myrow = buf + lane * BSTRIDE;
    const int e     = blockIdx.x * THREADS + threadIdx.x;
    const int ebase = blockIdx.x * THREADS + warp * 32;

    float* __restrict__ lat_out  = out;
    float* __restrict__ feat_out = out + (size_t)E * 128;
    float* __restrict__ cut_out  = out + (size_t)E * 416;

    // ---- per-edge loads ----
    const int   src = eidx[e];
    const int   dst = eidx[E + e];
    const float r   = elen[e];
    const float4 shv = reinterpret_cast<const float4*>(esh)[e];

    int ts = 0, td = 0;
    {
        const float4* rs = reinterpret_cast<const float4*>(onehot + (size_t)src * 16);
        const float4* rd = reinterpret_cast<const float4*>(onehot + (size_t)dst * 16);
#pragma unroll
        for (int q4 = 0; q4 < 4; q4++) {
            float4 a = __ldg(rs + q4); float4 b = __ldg(rd + q4);
            int base = q4 * 4;
            if (a.x > 0.5f) ts = base;     if (a.y > 0.5f) ts = base + 1;
            if (a.z > 0.5f) ts = base + 2; if (a.w > 0.5f) ts = base + 3;
            if (b.x > 0.5f) td = base;     if (b.y > 0.5f) td = base + 1;
            if (b.z > 0.5f) td = base + 2; if (b.w > 0.5f) td = base + 3;
        }
    }

    // ---- bessel + cutoff ----
    const float x    = r * 0.2f;
    const float invr = 1.0f / r;
    float eb[8];
#pragma unroll
    for (int j = 0; j < 8; j++)
        eb[j] = 0.4f * __sinf(sm[SM_CST + j] * x) * invr;

    const float x3 = x * x * x, x6 = x3 * x3, x7 = x6 * x, x8 = x7 * x;
    const float poly = 1.0f - 28.0f * x6 + 48.0f * x7 - 21.0f * x8;
    const float cutv = (x < 1.0f) ? poly : 0.0f;
    const float cl   = (cutv > 0.0f) ? cutv : 0.0f;
    cut_out[e] = cutv;

    // ---- stage 1: h[64] = silu( onehot-gather + eb @ W0 ) ----
    float hloc[64];  // local mem (dynamically indexed in rolled loops below)
    {
        u64 acc[32];
        const ulonglong2* w0s = reinterpret_cast<const ulonglong2*>(sm + SM_W0 + ts * 68);
        const ulonglong2* w0d = reinterpret_cast<const ulonglong2*>(sm + SM_W0 + (16 + td) * 68);
#pragma unroll
        for (int q = 0; q < 16; q++) {
            ulonglong2 a = w0s[q];
            ulonglong2 b = w0d[q];
            acc[2 * q]     = add2(a.x, b.x);
            acc[2 * q + 1] = add2(a.y, b.y);
        }
#pragma unroll
        for (int j = 0; j < 8; j++) {
            const u64 b2 = pk2(eb[j], eb[j]);
            const ulonglong2* wr = reinterpret_cast<const ulonglong2*>(sm + SM_W0 + (32 + j) * 68);
#pragma unroll
            for (int q = 0; q < 16; q++) {
                ulonglong2 w = wr[q];
                acc[2 * q]     = fma2(b2, w.x, acc[2 * q]);
                acc[2 * q + 1] = fma2(b2, w.y, acc[2 * q + 1]);
            }
        }
#pragma unroll
        for (int q = 0; q < 32; q++) {
            float a, b; up2(a, b, acc[q]);
            hloc[2 * q]     = silu_f(a);
            hloc[2 * q + 1] = silu_f(b);
        }
    }

    // ---- stage 2: lat[128] = cl * (h @ W1) ----
    const u64 cl2 = pk2(cl, cl);
#pragma unroll
    for (int p = 0; p < 2; p++) {
        u64 acc[32];
#pragma unroll
        for (int q = 0; q < 32; q++) acc[q] = 0ull;
        const float* wp = sm + SM_W1 + p * 64;
#pragma unroll 4
        for (int j = 0; j < 64; j++) {
            const float hj = hloc[j];
            const u64 h2 = pk2(hj, hj);
            const ulonglong2* wr = reinterpret_cast<const ulonglong2*>(wp + j * 128);
#pragma unroll
            for (int q = 0; q < 16; q++) {
                ulonglong2 w = wr[q];
                acc[2 * q]     = fma2(h2, w.x, acc[2 * q]);
                acc[2 * q + 1] = fma2(h2, w.y, acc[2 * q + 1]);
            }
        }
#pragma unroll
        for (int wdw = 0; wdw < 2; wdw++) {
#pragma unroll
            for (int q = 0; q < 8; q++) {
                float a0, a1, a2, a3;
                up2(a0, a1, mul2(cl2, acc[wdw * 16 + 2 * q]));
                up2(a2, a3, mul2(cl2, acc[wdw * 16 + 2 * q + 1]));
                *reinterpret_cast<float4*>(myrow + 4 * q) = make_float4(a0, a1, a2, a3);
            }
            __syncwarp();
            drain32(buf, lat_out, 128, ebase, p * 64 + wdw * 32, lane);
            __syncwarp();
        }
    }

    // ---- tensor-product scalars (cut folded) ----
    const float s = shv.x, vx = shv.y, vy = shv.z, vz = shv.w;
    const float tw0 = sm[SM_CST +  8], tw1 = sm[SM_CST +  9], tw2 = sm[SM_CST + 10];
    const float tw3 = sm[SM_CST + 11], tw4 = sm[SM_CST + 12], tw5 = sm[SM_CST + 13];
    const float tw6 = sm[SM_CST + 14];
    constexpr float SQ3  = 1.7320508075688772f;
    constexpr float INV2 = 0.70710678118654752f;

    const float sq   = s * s;
    const float dotv = (vx * vx + vy * vy + vz * vz) * (1.0f / SQ3);
    const float tp0a = (tw0 * sq + tw1 * dotv) * cl;
    const float tp0b = (tw4 * sq + tw5 * dotv) * cl;
    const float scl  = s * cl;
    float tp1a[3], tp1b[3];
    tp1a[0] = tw2 * scl * vx; tp1a[1] = tw2 * scl * vy; tp1a[2] = tw2 * scl * vz;
    tp1b[0] = tw3 * scl * vx; tp1b[1] = tw3 * scl * vy; tp1b[2] = tw3 * scl * vz;
    const float t6c = tw6 * cl;
    float tp2[5];
    tp2[0] = t6c * SQ3 * vx * vy;
    tp2[1] = t6c * SQ3 * vy * vz;
    tp2[2] = t6c * (vz * vz - 0.5f * (vx * vx + vy * vy));
    tp2[3] = t6c * SQ3 * vx * vz;
    tp2[4] = t6c * (0.5f * SQ3) * (vx * vx - vy * vy);

    // ---- f0: WC cols 0..63 ----
    {
        u64 acc[32];
#pragma unroll
        for (int q = 0; q < 32; q++) acc[q] = 0ull;
#pragma unroll 4
        for (int j = 0; j < 64; j++) {
            const float hj = hloc[j];
            const u64 l2 = pk2(hj, hj);
            const ulonglong2* wr = reinterpret_cast<const ulonglong2*>(sm + SM_WC + j * 160);
#pragma unroll
            for (int q = 0; q < 16; q++) {
                ulonglong2 w = wr[q];
                acc[2 * q]     = fma2(l2, w.x, acc[2 * q]);
                acc[2 * q + 1] = fma2(l2, w.y, acc[2 * q + 1]);
            }
        }
        float accf[64];
#pragma unroll
        for (int q = 0; q < 32; q++) up2(accf[2 * q], accf[2 * q + 1], acc[q]);
#pragma unroll
        for (int q = 0; q < 8; q++) {
            float4 v;
            v.x = INV2 * (accf[4 * q + 0] * tp0a + accf[32 + 4 * q + 0] * tp0b);
            v.y = INV2 * (accf[4 * q + 1] * tp0a + accf[32 + 4 * q + 1] * tp0b);
            v.z = INV2 * (accf[4 * q + 2] * tp0a + accf[32 + 4 * q + 2] * tp0b);
            v.w = INV2 * (accf[4 * q + 3] * tp0a + accf[32 + 4 * q + 3] * tp0b);
            *reinterpret_cast<float4*>(myrow + 4 * q) = v;
        }
        __syncwarp();
        drain32(buf, feat_out, 288, ebase, 0, lane);
        __syncwarp();
    }

    // ---- f1: WC cols 64..127 -> 96 outputs ----
    {
        u64 acc[32];
#pragma unroll
        for (int q = 0; q < 32; q++) acc[q] = 0ull;
#pragma unroll 4
        for (int j = 0; j < 64; j++) {
            const float hj = hloc[j];
            const u64 l2 = pk2(hj, hj);
            const ulonglong2* wr = reinterpret_cast<const ulonglong2*>(sm + SM_WC + j * 160 + 64);
#pragma unroll
            for (int q = 0; q < 16; q++) {
                ulonglong2 w = wr[q];
                acc[2 * q]     = fma2(l2, w.x, acc[2 * q]);
                acc[2 * q + 1] = fma2(l2, w.y, acc[2 * q + 1]);
            }
        }
        float accf[64];
#pragma unroll
        for (int q = 0; q < 32; q++) up2(accf[2 * q], accf[2 * q + 1], acc[q]);
#pragma unroll
        for (int t = 0; t < 3; t++) {
#pragma unroll
            for (int q = 0; q < 8; q++) {
                float4 v;
#pragma unroll
                for (int z = 0; z < 4; z++) {
                    const int cc = 32 * t + 4 * q + z, m = cc / 3, i = cc % 3;
                    const float val = INV2 * (accf[m] * tp1a[i] + accf[32 + m] * tp1b[i]);
                    if (z == 0) v.x = val; else if (z == 1) v.y = val;
                    else if (z == 2) v.z = val; else v.w = val;
                }
                *reinterpret_cast<float4*>(myrow + 4 * q) = v;
            }
            __syncwarp();
            drain32(buf, feat_out, 288, ebase, 32 + 32 * t, lane);
            __syncwarp();
        }
    }

    // ---- f2: WC cols 128..159 -> 160 outputs ----
    {
        u64 acc[16];
#pragma unroll
        for (int q = 0; q < 16; q++) acc[q] = 0ull;
#pragma unroll 4
        for (int j = 0; j < 64; j++) {
            const float hj = hloc[j];
            const u64 l2 = pk2(hj, hj);
            const ulonglong2* wr = reinterpret_cast<const ulonglong2*>(sm + SM_WC + j * 160 + 128);
#pragma unroll
            for (int q = 0; q < 8; q++) {
                ulonglong2 w = wr[q];
                acc[2 * q]     = fma2(l2, w.x, acc[2 * q]);
                acc[2 * q + 1] = fma2(l2, w.y, acc[2 * q + 1]);
            }
        }
        float accf[32];
#pragma unroll
        for (int q = 0; q < 16; q++) up2(accf[2 * q], accf[2 * q + 1], acc[q]);
#pragma unroll
        for (int t = 0; t < 5; t++) {
#pragma unroll
            for (int q = 0; q < 8; q++) {
                float4 v;
#pragma unroll
                for (int z = 0; z < 4; z++) {
                    const int cc = 32 * t + 4 * q + z, m = cc / 5, i = cc % 5;
                    const float val = accf[m] * tp2[i];
                    if (z == 0) v.x = val; else if (z == 1) v.y = val;
                    else if (z == 2) v.z = val; else v.w = val;
                }
                *reinterpret_cast<float4*>(myrow + 4 * q) = v;
            }
            __syncwarp();
            drain32(buf, feat_out, 288, ebase, 128 + 32 * t, lane);
            __syncwarp();
        }
    }
}

extern "C" void kernel_launch(void* const* d_in, const int* in_sizes, int n_in,
                              void* d_out, int out_size)
{
    const int*   eidx   = (const int*)  d_in[0];
    const float* esh    = (const float*)d_in[1];
    const float* elen   = (const float*)d_in[2];
    const float* onehot = (const float*)d_in[3];
    const float* bw     = (const float*)d_in[4];
    const float* tpw    = (const float*)d_in[5];
    const float* W0     = (const float*)d_in[6];
    const float* W1     = (const float*)d_in[7];
    const float* We     = (const float*)d_in[8];
    float* out = (float*)d_out;

    const int E = in_sizes[0] / 2;       // 524288
    const int blocks = E / THREADS;      // 1024

    combo_kernel<<<(64 * 160 + 255) / 256, 256>>>(W1, We);

    cudaFuncSetAttribute(e3_fused_kernel,
                         cudaFuncAttributeMaxDynamicSharedMemorySize, SMEM_BYTES);
    e3_fused_kernel<<<blocks, THREADS, SMEM_BYTES>>>(
        eidx, esh, elen, onehot, bw, tpw, W0, W1, out, E);
}

// round 10
// speedup vs baseline: 2.6018x; 1.6787x over previous
#include <cuda_runtime.h>
#include <cuda_bf16.h>
#include <cstdint>

typedef unsigned long long u64;

// ---------------- config ----------------
constexpr int TPB = 256;        // 8 warps
constexpr int EPB = 256;        // 1 edge per thread; warp owns 32 edges

// smem byte offsets
constexpr int OFF_AFH = 0;               // A-frags hi: 9216 u32 = 36864B
constexpr int OFF_AFL = 36864;           // A-frags lo: 36864B
constexpr int OFF_HHI = 73728;           // h hi: 256 edges x 35 u32 = 35840B
constexpr int OFF_HLO = 109568;          // h lo: 35840B
constexpr int OFF_TP  = 145408;          // tp: 256 x 16 f32 = 16384B
constexpr int OFF_BUF = 161792;          // 8 warps x 288 f32 = 9216B (stride 36 rows)
constexpr int OFF_BES = 171008;          // bessel W0 rows: 512 f32 = 2048B
constexpr int OFF_CST = 173056;          // 16 f32
constexpr int SMEM_BYTES = 173120;

constexpr int BSTR = 36;                 // D-buf row stride in floats (16B aligned)

// ---------------- device scratch ----------------
__device__ float    g_wcombo[64 * 160];
__device__ uint32_t g_afrag_hi[9216];    // 18 mtiles x 4 ktiles x 32 lanes x 4 regs
__device__ uint32_t g_afrag_lo[9216];

__device__ __forceinline__ float silu_f(float v) { return v / (1.0f + __expf(-v)); }

// ---------------- prep 1: W_combo = (W1*S1) @ (We*S2) ----------------
__global__ void combo_kernel(const float* __restrict__ W1, const float* __restrict__ We) {
    constexpr float S1 = 1.6789f * 0.125f;
    constexpr float S2 = 0.08838834764831845f;
    int idx = blockIdx.x * blockDim.x + threadIdx.x;
    if (idx >= 64 * 160) return;
    int r = idx / 160, c = idx % 160;
    float acc = 0.0f;
#pragma unroll 8
    for (int k = 0; k < 128; k++) acc = fmaf(W1[r * 128 + k], We[k * 160 + c], acc);
    g_wcombo[idx] = acc * (S1 * S2);
}

// packed weight element A[m][k] (A = Bpack^T), m in [0,288)
__device__ __forceinline__ float apack_val(int k, int m, const float* __restrict__ W1) {
    constexpr float S1 = 1.6789f * 0.125f;
    if (m < 128) return W1[k * 128 + m] * S1;
    if (m < 192) { int p = (m - 128) >> 1, s = (m - 128) & 1; return g_wcombo[k * 160 + p + 32 * s]; }
    if (m < 256) { int p = (m - 192) >> 1, s = (m - 192) & 1; return g_wcombo[k * 160 + 64 + p + 32 * s]; }
    return g_wcombo[k * 160 + 128 + (m - 256)];
}

// ---------------- prep 2: A fragments (hi/lo bf16) in mma order ----------------
// idx = ((mt*4 + kt)*32 + t)*4 + ri
// reg ri: m += (ri&1)*8 ; k += (ri>>1)*8 ; element pair (k, k+1) packed lo/hi
__global__ void afrag_kernel(const float* __restrict__ W1) {
    int idx = blockIdx.x * blockDim.x + threadIdx.x;
    if (idx >= 9216) return;
    int ri = idx & 3, t = (idx >> 2) & 31, kt = (idx >> 7) & 3, mt = idx >> 9;
    int m  = mt * 16 + (t >> 2) + (ri & 1) * 8;
    int k0 = kt * 16 + (t & 3) * 2 + (ri >> 1) * 8;
    uint32_t hi = 0, lo = 0;
#pragma unroll
    for (int hv = 0; hv < 2; hv++) {
        float val = apack_val(k0 + hv, m, W1);
        __nv_bfloat16 h = __float2bfloat16(val);
        float rem = val - __bfloat162float(h);
        __nv_bfloat16 l = __float2bfloat16(rem);
        hi |= (uint32_t)__bfloat16_as_ushort(h) << (16 * hv);
        lo |= (uint32_t)__bfloat16_as_ushort(l) << (16 * hv);
    }
    g_afrag_hi[idx] = hi;
    g_afrag_lo[idx] = lo;
}

// ---------------- mma helper ----------------
__device__ __forceinline__ void mma16816(float* d, const uint4& a, uint32_t b0, uint32_t b1) {
    asm volatile(
        "mma.sync.aligned.m16n8k16.row.col.f32.bf16.bf16.f32 "
        "{%0,%1,%2,%3}, {%4,%5,%6,%7}, {%8,%9}, {%0,%1,%2,%3};"
        : "+f"(d[0]), "+f"(d[1]), "+f"(d[2]), "+f"(d[3])
        : "r"(a.x), "r"(a.y), "r"(a.z), "r"(a.w), "r"(b0), "r"(b1));
}

// ---------------- main kernel ----------------
__global__ void __launch_bounds__(TPB, 1)
e3_mma_kernel(const int*   __restrict__ eidx,
              const float* __restrict__ esh,
              const float* __restrict__ elen,
              const float* __restrict__ onehot,
              const float* __restrict__ bw,
              const float* __restrict__ tpw,
              const float* __restrict__ W0,
              float*       __restrict__ out,
              int E)
{
    extern __shared__ __align__(16) char smc[];
    const int tid  = threadIdx.x;
    const int warp = tid >> 5;
    const int lane = tid & 31;
    const int t3   = lane & 3;
    const int g    = lane >> 2;

    // ---- cooperative loads ----
    {
        uint4* afh = reinterpret_cast<uint4*>(smc + OFF_AFH);
        uint4* afl = reinterpret_cast<uint4*>(smc + OFF_AFL);
        const uint4* gh = reinterpret_cast<const uint4*>(g_afrag_hi);
        const uint4* gl = reinterpret_cast<const uint4*>(g_afrag_lo);
#pragma unroll
        for (int i = 0; i < 9; i++) {                 // 2304 uint4 each
            afh[tid + i * TPB] = gh[tid + i * TPB];
            afl[tid + i * TPB] = gl[tid + i * TPB];
        }
        float* bes = reinterpret_cast<float*>(smc + OFF_BES);
        bes[tid]       = W0[32 * 64 + tid];
        bes[tid + 256] = W0[32 * 64 + 256 + tid];
        float* cst = reinterpret_cast<float*>(smc + OFF_CST);
        if (tid < 8)       cst[tid] = bw[tid];
        else if (tid < 15) cst[tid] = tpw[tid - 8];
    }
    __syncthreads();

    const float* bes = reinterpret_cast<const float*>(smc + OFF_BES);
    const float* cst = reinterpret_cast<const float*>(smc + OFF_CST);
    float* tparr = reinterpret_cast<float*>(smc + OFF_TP);

    float* __restrict__ lat_out  = out;
    float* __restrict__ feat_out = out + (size_t)E * 128;
    float* __restrict__ cut_out  = out + (size_t)E * 416;

    // ================= stage 1: per-thread edge =================
    {
        const int e = blockIdx.x * EPB + tid;
        const int   src = eidx[e];
        const int   dst = eidx[E + e];
        const float r   = elen[e];
        const float4 shv = reinterpret_cast<const float4*>(esh)[e];

        int ts = 0, td = 0;
        {
            const float4* rs = reinterpret_cast<const float4*>(onehot + (size_t)src * 16);
            const float4* rd = reinterpret_cast<const float4*>(onehot + (size_t)dst * 16);
#pragma unroll
            for (int q4 = 0; q4 < 4; q4++) {
                float4 a = __ldg(rs + q4); float4 b = __ldg(rd + q4);
                int base = q4 * 4;
                if (a.x > 0.5f) ts = base;     if (a.y > 0.5f) ts = base + 1;
                if (a.z > 0.5f) ts = base + 2; if (a.w > 0.5f) ts = base + 3;
                if (b.x > 0.5f) td = base;     if (b.y > 0.5f) td = base + 1;
                if (b.z > 0.5f) td = base + 2; if (b.w > 0.5f) td = base + 3;
            }
        }

        const float x    = r * 0.2f;
        const float invr = 1.0f / r;
        float eb[8];
#pragma unroll
        for (int j = 0; j < 8; j++)
            eb[j] = 0.4f * __sinf(cst[j] * x) * invr;

        const float x3 = x * x * x, x6 = x3 * x3, x7 = x6 * x, x8 = x7 * x;
        const float poly = 1.0f - 28.0f * x6 + 48.0f * x7 - 21.0f * x8;
        const float cutv = (x < 1.0f) ? poly : 0.0f;
        const float cl   = (cutv > 0.0f) ? cutv : 0.0f;
        cut_out[e] = cutv;

        // h = silu(S0*(W0[ts] + W0[16+td] + eb @ bessel_rows))
        constexpr float S0 = 0.15811388300841897f;
        float h[64];
        {
            const float4* rowts = reinterpret_cast<const float4*>(W0 + ts * 64);
            const float4* rowtd = reinterpret_cast<const float4*>(W0 + (16 + td) * 64);
#pragma unroll
            for (int q = 0; q < 16; q++) {
                float4 a = __ldg(rowts + q);
                float4 b = __ldg(rowtd + q);
                h[4 * q + 0] = a.x + b.x; h[4 * q + 1] = a.y + b.y;
                h[4 * q + 2] = a.z + b.z; h[4 * q + 3] = a.w + b.w;
            }
#pragma unroll
            for (int j = 0; j < 8; j++) {
                const float bj = eb[j];
                const float4* br = reinterpret_cast<const float4*>(bes + j * 64);
#pragma unroll
                for (int q = 0; q < 16; q++) {
                    float4 w = br[q];
                    h[4 * q + 0] = fmaf(bj, w.x, h[4 * q + 0]);
                    h[4 * q + 1] = fmaf(bj, w.y, h[4 * q + 1]);
                    h[4 * q + 2] = fmaf(bj, w.z, h[4 * q + 2]);
                    h[4 * q + 3] = fmaf(bj, w.w, h[4 * q + 3]);
                }
            }
        }

        // split h -> bf16 hi/lo; store pairs (stride 35 u32 per edge)
        uint32_t* hh = reinterpret_cast<uint32_t*>(smc + OFF_HHI) + tid * 35;
        uint32_t* hl = reinterpret_cast<uint32_t*>(smc + OFF_HLO) + tid * 35;
#pragma unroll
        for (int q = 0; q < 32; q++) {
            float v0 = silu_f(S0 * h[2 * q]);
            float v1 = silu_f(S0 * h[2 * q + 1]);
            __nv_bfloat16 h0 = __float2bfloat16(v0), h1 = __float2bfloat16(v1);
            float r0 = v0 - __bfloat162float(h0);
            float r1 = v1 - __bfloat162float(h1);
            __nv_bfloat16 l0 = __float2bfloat16(r0), l1 = __float2bfloat16(r1);
            hh[q] = (uint32_t)__bfloat16_as_ushort(h0) | ((uint32_t)__bfloat16_as_ushort(h1) << 16);
            hl[q] = (uint32_t)__bfloat16_as_ushort(l0) | ((uint32_t)__bfloat16_as_ushort(l1) << 16);
        }

        // tp scalars (cut + INV2 folded)
        constexpr float SQ3  = 1.7320508075688772f;
        constexpr float INV2 = 0.70710678118654752f;
        const float s = shv.x, vx = shv.y, vy = shv.z, vz = shv.w;
        const float tw0 = cst[8],  tw1 = cst[9],  tw2 = cst[10];
        const float tw3 = cst[11], tw4 = cst[12], tw5 = cst[13];
        const float tw6 = cst[14];
        const float sq   = s * s;
        const float dotv = (vx * vx + vy * vy + vz * vz) * (1.0f / SQ3);
        float* tp = tparr + tid * 16;
        tp[0] = cl;
        tp[1] = INV2 * (tw0 * sq + tw1 * dotv) * cl;
        tp[2] = INV2 * (tw4 * sq + tw5 * dotv) * cl;
        const float sa = INV2 * tw2 * s * cl;
        const float sb = INV2 * tw3 * s * cl;
        tp[3] = sa * vx; tp[4] = sa * vy; tp[5] = sa * vz;
        tp[6] = sb * vx; tp[7] = sb * vy; tp[8] = sb * vz;
        const float t6c = tw6 * cl;
        tp[9]  = t6c * SQ3 * vx * vy;
        tp[10] = t6c * SQ3 * vy * vz;
        tp[11] = t6c * (vz * vz - 0.5f * (vx * vx + vy * vy));
        tp[12] = t6c * SQ3 * vx * vz;
        tp[13] = t6c * (0.5f * SQ3) * (vx * vx - vy * vy);
    }
    __syncwarp();   // h/tp written & read within the same warp

    // ================= GEMM via mma.sync =================
    const uint4* afh = reinterpret_cast<const uint4*>(smc + OFF_AFH);
    const uint4* afl = reinterpret_cast<const uint4*>(smc + OFF_AFL);
    const uint32_t* hh = reinterpret_cast<const uint32_t*>(smc + OFF_HHI);
    const uint32_t* hl = reinterpret_cast<const uint32_t*>(smc + OFF_HLO);
    float* bwarp = reinterpret_cast<float*>(smc + OFF_BUF) + warp * (8 * BSTR);

#pragma unroll 1
    for (int c = 0; c < 9; c++) {
#pragma unroll 1
        for (int ngp = 0; ngp < 2; ngp++) {
            float acc[2][2][4];
#pragma unroll
            for (int a = 0; a < 2; a++)
#pragma unroll
                for (int b = 0; b < 2; b++)
#pragma unroll
                    for (int q = 0; q < 4; q++) acc[a][b][q] = 0.0f;

            const int eb0 = (warp * 32 + ngp * 16 + g) * 35 + t3;
            const int eb1 = eb0 + 8 * 35;

#pragma unroll
            for (int kt = 0; kt < 4; kt++) {
                const int ai = (2 * c * 4 + kt) * 32 + lane;
                const uint4 ah0 = afh[ai];
                const uint4 ah1 = afh[ai + 128];
                const uint4 al0 = afl[ai];
                const uint4 al1 = afl[ai + 128];
                const int ko = kt * 8;
                const uint32_t bh0a = hh[eb0 + ko], bh0b = hh[eb0 + ko + 4];
                const uint32_t bl0a = hl[eb0 + ko], bl0b = hl[eb0 + ko + 4];
                const uint32_t bh1a = hh[eb1 + ko], bh1b = hh[eb1 + ko + 4];
                const uint32_t bl1a = hl[eb1 + ko], bl1b = hl[eb1 + ko + 4];

                mma16816(acc[0][0], ah0, bh0a, bh0b);
                mma16816(acc[0][1], ah1, bh0a, bh0b);
                mma16816(acc[1][0], ah0, bh1a, bh1b);
                mma16816(acc[1][1], ah1, bh1a, bh1b);
                mma16816(acc[0][0], ah0, bl0a, bl0b);
                mma16816(acc[0][1], ah1, bl0a, bl0b);
                mma16816(acc[1][0], ah0, bl1a, bl1b);
                mma16816(acc[1][1], ah1, bl1a, bl1b);
                mma16816(acc[0][0], al0, bh0a, bh0b);
                mma16816(acc[0][1], al1, bh0a, bh0b);
                mma16816(acc[1][0], al0, bh1a, bh1b);
                mma16816(acc[1][1], al1, bh1a, bh1b);
            }

            // ---- epilogue per n-group ----
#pragma unroll 1
            for (int ng2 = 0; ng2 < 2; ng2++) {
                const int ng = 2 * ngp + ng2;
                // scatter D frags to buf[edge][m] (stride BSTR)
#pragma unroll
                for (int mtc = 0; mtc < 2; mtc++) {
                    bwarp[(2 * t3)     * BSTR + mtc * 16 + g]     = acc[ng2][mtc][0];
                    bwarp[(2 * t3 + 1) * BSTR + mtc * 16 + g]     = acc[ng2][mtc][1];
                    bwarp[(2 * t3)     * BSTR + mtc * 16 + g + 8] = acc[ng2][mtc][2];
                    bwarp[(2 * t3 + 1) * BSTR + mtc * 16 + g + 8] = acc[ng2][mtc][3];
                }
                __syncwarp();

                const int el = warp * 32 + ng * 8 + g;          // block-local edge
                const size_t eg = (size_t)blockIdx.x * EPB + el;
                const float* tp  = tparr + el * 16;
                const float* row = bwarp + g * BSTR;

                if (c < 4) {
                    const float cl = tp[0];
#pragma unroll
                    for (int h2 = 0; h2 < 2; h2++) {
                        float4 v = *reinterpret_cast<const float4*>(row + t3 * 8 + 4 * h2);
                        v.x *= cl; v.y *= cl; v.z *= cl; v.w *= cl;
                        *reinterpret_cast<float4*>(lat_out + eg * 128 + c * 32 + t3 * 8 + 4 * h2) = v;
                    }
                } else if (c < 6) {
                    const float ta = tp[1], tb = tp[2];
                    float4 v;
                    v.x = row[8 * t3 + 0] * ta + row[8 * t3 + 1] * tb;
                    v.y = row[8 * t3 + 2] * ta + row[8 * t3 + 3] * tb;
                    v.z = row[8 * t3 + 4] * ta + row[8 * t3 + 5] * tb;
                    v.w = row[8 * t3 + 6] * ta + row[8 * t3 + 7] * tb;
                    *reinterpret_cast<float4*>(feat_out + eg * 288 + (c - 4) * 16 + 4 * t3) = v;
                } else if (c < 8) {
                    float v[12];
#pragma unroll
                    for (int j = 0; j < 4; j++) {
                        const float a = row[8 * t3 + 2 * j], b = row[8 * t3 + 2 * j + 1];
                        v[3 * j + 0] = a * tp[3] + b * tp[6];
                        v[3 * j + 1] = a * tp[4] + b * tp[7];
                        v[3 * j + 2] = a * tp[5] + b * tp[8];
                    }
                    float* dst = feat_out + eg * 288 + 32 + (c - 6) * 48 + 12 * t3;
#pragma unroll
                    for (int t = 0; t < 3; t++)
                        reinterpret_cast<float4*>(dst)[t] =
                            make_float4(v[4 * t], v[4 * t + 1], v[4 * t + 2], v[4 * t + 3]);
                } else {
                    float v[40];
#pragma unroll
                    for (int j = 0; j < 8; j++) {
                        const float a = row[8 * t3 + j];
#pragma unroll
                        for (int i = 0; i < 5; i++) v[5 * j + i] = a * tp[9 + i];
                    }
                    float* dst = feat_out + eg * 288 + 128 + 40 * t3;
#pragma unroll
                    for (int t = 0; t < 10; t++)
                        reinterpret_cast<float4*>(dst)[t] =
                            make_float4(v[4 * t], v[4 * t + 1], v[4 * t + 2], v[4 * t + 3]);
                }
                __syncwarp();
            }
        }
    }
}

extern "C" void kernel_launch(void* const* d_in, const int* in_sizes, int n_in,
                              void* d_out, int out_size)
{
    const int*   eidx   = (const int*)  d_in[0];
    const float* esh    = (const float*)d_in[1];
    const float* elen   = (const float*)d_in[2];
    const float* onehot = (const float*)d_in[3];
    const float* bw     = (const float*)d_in[4];
    const float* tpw    = (const float*)d_in[5];
    const float* W0     = (const float*)d_in[6];
    const float* W1     = (const float*)d_in[7];
    const float* We     = (const float*)d_in[8];
    float* out = (float*)d_out;

    const int E = in_sizes[0] / 2;       // 524288
    const int blocks = E / EPB;          // 2048

    combo_kernel<<<(64 * 160 + 255) / 256, 256>>>(W1, We);
    afrag_kernel<<<(9216 + 255) / 256, 256>>>(W1);

    cudaFuncSetAttribute(e3_mma_kernel,
                         cudaFuncAttributeMaxDynamicSharedMemorySize, SMEM_BYTES);
    e3_mma_kernel<<<blocks, TPB, SMEM_BYTES>>>(
        eidx, esh, elen, onehot, bw, tpw, W0, out, E);
}